// round 10
// baseline (speedup 1.0000x reference)
#include <cuda_runtime.h>
#include <math.h>

#define Bn 8
#define Cc 64
#define Hh 128
#define Ww 128
#define Gg 4
#define CG 16
#define HW (Hh*Ww)          // 16384
#define CHW (Cc*HW)         // 1048576
#define SZ (Bn*CHW)         // 8388608
#define NR (Bn*Hh)          // 1024
#define TH 4
#define SP 129              // sS/sM pitch (odd, conflict-free)
#define AP 67               // sA pitch (odd, conflict-free)
#define TP 129              // T buffer pitch
#define CP 136
#define CICSZ (6*CP)

typedef unsigned long long u64;

__device__ __forceinline__ u64 pk2(float lo, float hi) {
    u64 r;
    asm("mov.b64 %0, {%1, %2};" : "=l"(r)
        : "r"(__float_as_uint(lo)), "r"(__float_as_uint(hi)));
    return r;
}
__device__ __forceinline__ void upk2(u64 p, float& lo, float& hi) {
    unsigned a, bq;
    asm("mov.b64 {%0, %1}, %2;" : "=r"(a), "=r"(bq) : "l"(p));
    lo = __uint_as_float(a); hi = __uint_as_float(bq);
}
#define FMA2(d, a, b) asm("fma.rn.f32x2 %0, %1, %2, %3;" : "=l"(d) : "l"(a), "l"(b), "l"(d))

__device__ float g_t[2*SZ];
__device__ float g_r[2*SZ];
__device__ float g_stats[2][2][Cc];

// ---------------- BN batch statistics ----------------
__global__ void __launch_bounds__(256) k_bnstats(const float* __restrict__ xl,
                                                 const float* __restrict__ xr,
                                                 const float* __restrict__ gamma,
                                                 const float* __restrict__ beta) {
    int c = blockIdx.x, side = blockIdx.y;
    const float* x = side ? xr : xl;
    int tid = threadIdx.x;
    float s = 0.f, s2 = 0.f;
    for (int b = 0; b < Bn; b++) {
        const float* p = x + b*CHW + c*HW;
        for (int i = tid; i < HW; i += 256) {
            float v = p[i];
            s += v; s2 = fmaf(v, v, s2);
        }
    }
    __shared__ float sh[256], sh2[256];
    sh[tid] = s; sh2[tid] = s2;
    __syncthreads();
    for (int off = 128; off; off >>= 1) {
        if (tid < off) { sh[tid] += sh[tid+off]; sh2[tid] += sh2[tid+off]; }
        __syncthreads();
    }
    if (tid == 0) {
        double N = (double)(Bn*HW);
        double m = (double)sh[0] / N;
        double var = (double)sh2[0] / N - m*m;
        double rstd = 1.0 / sqrt(var + 1e-5);
        float a = gamma[c] * (float)rstd;
        float d = beta[c] - a * (float)m;
        g_stats[side][0][c] = a;
        g_stats[side][1][c] = d;
    }
}

// ---------------- grouped 3x3 conv (unchanged from R8/R9) ----------------
template<bool FIRST>
__global__ void __launch_bounds__(256) k_conv3(const float* __restrict__ xl,
                                               const float* __restrict__ xr,
                                               const float* __restrict__ wgt,
                                               const float* __restrict__ bias) {
    int ty = blockIdx.x, g = blockIdx.y;
    int side = blockIdx.z >> 3, b = blockIdx.z & 7;
    const float* xraw = side ? xr : xl;
    const float* in   = FIRST ? xraw : (g_t + side*SZ);
    float* out        = FIRST ? (g_t + side*SZ) : (g_r + side*SZ);

    extern __shared__ float sm[];
    float* sIn = sm;
    float* sW2 = sm + 13056;
    __shared__ float sa[CG], sd[CG];
    int tid = threadIdx.x;

    if (tid < CG) {
        sa[tid] = g_stats[side][0][g*CG + tid];
        sd[tid] = g_stats[side][1][g*CG + tid];
    }
    __syncthreads();

    for (int i = tid; i < 2304; i += 256) {
        int o = i & 15, rem = i >> 4;
        int k = rem % 9, ic = rem / 9;
        sW2[i] = wgt[g*2304 + (o*16 + ic)*9 + k];
    }

    for (int i = tid; i < 96; i += 256) {
        int ic = i / 6, r = i - ic*6;
        sIn[ic*CICSZ + r*CP + 3]   = 0.f;
        sIn[ic*CICSZ + r*CP + 132] = 0.f;
    }

    {
        int x4 = tid & 31, rowid = tid >> 5;
        int y0 = ty*TH - 1;
        const float* inb = in + b*CHW + g*CG*HW;
#pragma unroll
        for (int s = rowid; s < 96; s += 8) {
            int ic = s / 6, r = s - ic*6;
            int y = y0 + r;
            float4 v4 = make_float4(0.f, 0.f, 0.f, 0.f);
            if ((unsigned)y < (unsigned)Hh) {
                v4 = *(const float4*)(inb + ic*HW + y*Ww + x4*4);
                if (FIRST) {
                    float a = sa[ic], d = sd[ic];
                    v4.x = fmaf(a, v4.x, d);
                    v4.y = fmaf(a, v4.y, d);
                    v4.z = fmaf(a, v4.z, d);
                    v4.w = fmaf(a, v4.w, d);
                }
            }
            *(float4*)(sIn + ic*CICSZ + r*CP + 4 + x4*4) = v4;
        }
    }
    __syncthreads();

    int xcol = tid & 127, half = tid >> 7;
    u64 acc2[4][TH];
#pragma unroll
    for (int o2 = 0; o2 < 4; o2++) {
        u64 bp = pk2(bias[g*CG + half*8 + 2*o2], bias[g*CG + half*8 + 2*o2 + 1]);
#pragma unroll
        for (int r = 0; r < TH; r++) acc2[o2][r] = bp;
    }

    for (int ic = 0; ic < CG; ic++) {
        const float* ip = sIn + ic*CICSZ;
#pragma unroll
        for (int k = 0; k < 9; k++) {
            int dy = k / 3, dx = k - dy*3;
            const ulonglong2* wq = (const ulonglong2*)(sW2 + (ic*9 + k)*16 + half*8);
            ulonglong2 wA = wq[0], wB = wq[1];
#pragma unroll
            for (int r = 0; r < TH; r++) {
                float iv = ip[(r+dy)*CP + xcol + 3 + dx];
                u64 piv = pk2(iv, iv);
                FMA2(acc2[0][r], wA.x, piv);
                FMA2(acc2[1][r], wA.y, piv);
                FMA2(acc2[2][r], wB.x, piv);
                FMA2(acc2[3][r], wB.y, piv);
            }
        }
    }

    int ybase = ty*TH;
#pragma unroll
    for (int o2 = 0; o2 < 4; o2++) {
        int ocl0 = half*8 + 2*o2;
        int gbase = b*CHW + (g*CG + ocl0)*HW + ybase*Ww + xcol;
#pragma unroll
        for (int r = 0; r < TH; r++) {
            float v0, v1;
            upk2(acc2[o2][r], v0, v1);
            if (FIRST) {
                v0 = v0 > 0.f ? v0 : 0.1f*v0;
                v1 = v1 > 0.f ? v1 : 0.1f*v1;
            } else {
                v0 += fmaf(sa[ocl0],   xraw[gbase + r*Ww],      sd[ocl0]);
                v1 += fmaf(sa[ocl0+1], xraw[gbase + HW + r*Ww], sd[ocl0+1]);
            }
            out[gbase + r*Ww]      = v0;
            out[gbase + HW + r*Ww] = v1;
        }
    }
}

// ---------------- fused attention ----------------
// smem floats: sA[128][67]=8576 @0 | sB[64][132]=8448 @8576 | sS[128][129]=16512 @17024
//              sXl @33536 (8704) | sXr @42240 (8704) ; end 50944
// overlays: sM[128][129] @0 (over sA+sB); T[128][129] @33536 (over sXl/sXr)
#define ATT_SMEM (50944*4)
#define NT 1024
__global__ void __launch_bounds__(NT) k_attn(const float* __restrict__ xl,
                                             const float* __restrict__ xr,
                                             const float* __restrict__ qw, const float* __restrict__ qb,
                                             const float* __restrict__ kw, const float* __restrict__ kb,
                                             float* __restrict__ out) {
    int n = blockIdx.x, b = n >> 7, h = n & 127;
    extern __shared__ float sm[];
    float* sA  = sm;
    float* sB  = sm + 8576;
    float* sS  = sm + 17024;
    float* sXl = sm + 33536;
    float* sXr = sm + 42240;
    float* sM  = sm;                  // overlay
    float* sT  = sm + 33536;          // overlay (valid after transport GEMM)
    __shared__ float sWq[2048];
    __shared__ float sBias[128];
    __shared__ float sMean[128];
    __shared__ float sV[2][128];
    __shared__ float sPart[NT];
    int tid = threadIdx.x, lane = tid & 31, w = tid >> 5;

    // ---- phase 0: weights/bias
    for (int idx = tid; idx < 2048; idx += NT) {
        int side = idx >> 10, rem = idx & 1023, i = rem >> 6, o = rem & 63;
        sWq[idx] = (side ? kw : qw)[o*16 + i];
    }
    if (tid < 64) { sBias[tid] = qb[tid]; sBias[64 + tid] = kb[tid]; }
    __syncthreads();

    // X staging
    for (int idx = tid; idx < 8192; idx += NT) {
        int c = idx >> 7, x = idx & 127;
        sXl[x*68 + c] = xl[b*CHW + c*HW + h*Ww + x];
        sXr[x*68 + c] = xr[b*CHW + c*HW + h*Ww + x];
    }

    // ---- phase 1: grouped 1x1 Q/K conv, R direct from global
    {
        int side = tid >> 9, rem = tid & 511;
        int g = rem >> 7, x = rem & 127;
        const float* Rg = (side ? g_r + SZ : g_r) + b*CHW + h*Ww + g*16*HW + x;
        const u64* bp = (const u64*)(sBias + side*64 + g*16);
        u64 acc[8];
#pragma unroll
        for (int j = 0; j < 8; j++) acc[j] = bp[j];
#pragma unroll
        for (int i = 0; i < 16; i++) {
            float rv = Rg[(unsigned)(i*HW)];
            u64 prv = pk2(rv, rv);
            const u64* wp = (const u64*)(sWq + side*1024 + i*64 + g*16);
#pragma unroll
            for (int j = 0; j < 8; j++) FMA2(acc[j], wp[j], prv);
        }
        if (side == 0) {
            float* dst = sA + x*AP + g*16;
#pragma unroll
            for (int j = 0; j < 8; j++) {
                float a0, a1; upk2(acc[j], a0, a1);
                dst[2*j] = a0; dst[2*j + 1] = a1;
            }
        } else {
            float* dst = sB + (g*16)*132 + x;
#pragma unroll
            for (int j = 0; j < 8; j++) {
                float a0, a1; upk2(acc[j], a0, a1);
                dst[(2*j)*132]   = a0;
                dst[(2*j+1)*132] = a1;
            }
        }
    }
    __syncthreads();

    // ---- phase 2: per-channel row means, subtract
    for (int task = w; task < 128; task += 32) {
        float s = 0.f;
        if (task < 64) {
#pragma unroll
            for (int k = 0; k < 4; k++) s += sA[(lane + 32*k)*AP + task];
        } else {
#pragma unroll
            for (int k = 0; k < 4; k++) s += sB[(task - 64)*132 + lane + 32*k];
        }
#pragma unroll
        for (int off = 16; off; off >>= 1) s += __shfl_xor_sync(0xffffffffu, s, off);
        if (lane == 0) sMean[task] = s * (1.f/128.f);
    }
    __syncthreads();
    for (int idx = tid; idx < 8192; idx += NT) {
        int c = idx >> 7, u = idx & 127;
        sA[u*AP + c]  -= sMean[c];
        sB[c*132 + u] -= sMean[64 + c];
    }
    __syncthreads();

    // ---- phase 3: score GEMM, lane owns u (32u x 16v per warp), raw S -> sS
    {
        int u = (w & 3)*32 + lane;
        int v0 = (w >> 2)*16;
        u64 acc2[8];
#pragma unroll
        for (int j = 0; j < 8; j++) acc2[j] = 0ull;
        for (int c = 0; c < 64; c++) {
            float a = sA[u*AP + c];
            u64 pa = pk2(a, a);
            const ulonglong2* kp = (const ulonglong2*)(sB + c*132 + v0);
            ulonglong2 q0 = kp[0], q1 = kp[1];
            FMA2(acc2[0], pa, q0.x);
            FMA2(acc2[1], pa, q0.y);
            FMA2(acc2[2], pa, q1.x);
            FMA2(acc2[3], pa, q1.y);
            kp += 2;
            ulonglong2 q2 = kp[0], q3 = kp[1];
            FMA2(acc2[4], pa, q2.x);
            FMA2(acc2[5], pa, q2.y);
            FMA2(acc2[6], pa, q3.x);
            FMA2(acc2[7], pa, q3.y);
        }
        float* sp = sS + u*SP + v0;
#pragma unroll
        for (int j = 0; j < 8; j++) {
            float l0, h0; upk2(acc2[j], l0, h0);
            sp[2*j] = l0; sp[2*j + 1] = h0;
        }
    }
    __syncthreads();

    // ---- phase 4a: row softmax (sS -> sM); sA/sB dead now
    {
        int r0 = w*4;
#pragma unroll
        for (int r = r0; r < r0 + 4; r++) {
            float x4[4]; float m = -1e30f;
#pragma unroll
            for (int k = 0; k < 4; k++) { x4[k] = sS[r*SP + lane + 32*k]; m = fmaxf(m, x4[k]); }
#pragma unroll
            for (int off = 16; off; off >>= 1) m = fmaxf(m, __shfl_xor_sync(0xffffffffu, m, off));
            float e4[4]; float s = 0.f;
#pragma unroll
            for (int k = 0; k < 4; k++) { e4[k] = __expf(x4[k] - m); s += e4[k]; }
#pragma unroll
            for (int off = 16; off; off >>= 1) s += __shfl_xor_sync(0xffffffffu, s, off);
            float inv = 1.f / s;
#pragma unroll
            for (int k = 0; k < 4; k++) sM[r*SP + lane + 32*k] = e4[k] * inv;
        }
    }
    __syncthreads();
    // ---- phase 4b: column softmax in place (sS[u][v] <- M_lr[v][u])
    for (int c = w; c < 128; c += 32) {
        float x4[4]; float m = -1e30f;
#pragma unroll
        for (int k = 0; k < 4; k++) { x4[k] = sS[(lane + 32*k)*SP + c]; m = fmaxf(m, x4[k]); }
#pragma unroll
        for (int off = 16; off; off >>= 1) m = fmaxf(m, __shfl_xor_sync(0xffffffffu, m, off));
        float e4[4]; float s = 0.f;
#pragma unroll
        for (int k = 0; k < 4; k++) { e4[k] = __expf(x4[k] - m); s += e4[k]; }
#pragma unroll
        for (int off = 16; off; off >>= 1) s += __shfl_xor_sync(0xffffffffu, s, off);
        float inv = 1.f / s;
#pragma unroll
        for (int k = 0; k < 4; k++) sS[(lane + 32*k)*SP + c] = e4[k] * inv;
    }
    __syncthreads();

    // ---- phase 5: transport GEMM (accs stay in registers; blend deferred)
    int t_side = w >> 4, t_u = ((w >> 2) & 3)*32 + lane, t_c0 = (w & 3)*16;
    u64 tacc[8];
#pragma unroll
    for (int j = 0; j < 8; j++) tacc[j] = 0ull;
    {
        const float* X = t_side ? sXl : sXr;
        for (int v = 0; v < 128; v++) {
            float a = t_side ? sS[v*SP + t_u] : sM[t_u*SP + v];
            u64 pa = pk2(a, a);
            const ulonglong2* xp = (const ulonglong2*)(X + v*68 + t_c0);
            ulonglong2 xA = xp[0], xB = xp[1];
            FMA2(tacc[0], pa, xA.x);
            FMA2(tacc[1], pa, xA.y);
            FMA2(tacc[2], pa, xB.x);
            FMA2(tacc[3], pa, xB.y);
            xp += 2;
            ulonglong2 xC = xp[0], xD = xp[1];
            FMA2(tacc[4], pa, xC.x);
            FMA2(tacc[5], pa, xC.y);
            FMA2(tacc[6], pa, xD.x);
            FMA2(tacc[7], pa, xD.y);
        }
    }
    __syncthreads();   // sXl/sXr now dead -> T buffer

    // ---- phase 6a: T = 5-tap over rows of sM
    {
        int v = tid & 127, u0 = (tid >> 7)*16;
        float a0 = (u0 >= 2) ? sM[(u0-2)*SP + v] : 0.f;
        float a1 = (u0 >= 1) ? sM[(u0-1)*SP + v] : 0.f;
        float a2 = sM[u0*SP + v];
        float a3 = sM[(u0+1)*SP + v];
        float S4 = a0 + a1 + a2 + a3;
#pragma unroll
        for (int k = 0; k < 16; k++) {
            int u = u0 + k;
            float a4 = (u + 2 < 128) ? sM[(u+2)*SP + v] : 0.f;
            sT[u*TP + v] = S4 + a4;
            S4 = S4 + a4 - a0;
            a0 = a1; a1 = a2; a2 = a3; a3 = a4;
        }
    }
    __syncthreads();
    // ---- phase 6b: dot T . sS -> V_left partials
    {
        int u = tid & 127, v0 = (tid >> 7)*16;
        float accv = 0.f;
#pragma unroll
        for (int k = 0; k < 16; k++) {
            int v = v0 + k;
            accv = fmaf(sT[u*TP + v], sS[u*SP + v], accv);
        }
        sPart[tid] = accv;
    }
    __syncthreads();
    if (tid < 128) {
        float s = 0.f;
#pragma unroll
        for (int k = 0; k < 8; k++) s += sPart[tid + 128*k];
        sV[0][tid] = tanhf(5.f * s);
    }
    // ---- phase 6c: T' = 5-tap over u-index of sS (contiguous direction)
    {
        int v = tid & 127, u0 = (tid >> 7)*16;
        float a0 = (u0 >= 2) ? sS[v*SP + u0-2] : 0.f;
        float a1 = (u0 >= 1) ? sS[v*SP + u0-1] : 0.f;
        float a2 = sS[v*SP + u0];
        float a3 = sS[v*SP + u0+1];
        float S4 = a0 + a1 + a2 + a3;
        __syncthreads();   // ensure 6b reads of sT complete before overwrite
#pragma unroll
        for (int k = 0; k < 16; k++) {
            int u = u0 + k;
            float a4 = (u + 2 < 128) ? sS[v*SP + u+2] : 0.f;
            sT[v*TP + u] = S4 + a4;
            S4 = S4 + a4 - a0;
            a0 = a1; a1 = a2; a2 = a3; a3 = a4;
        }
    }
    __syncthreads();
    // ---- phase 6d: dot T' . sM -> V_right partials
    {
        int u = tid & 127, v0 = (tid >> 7)*16;
        float accv = 0.f;
#pragma unroll
        for (int k = 0; k < 16; k++) {
            int v = v0 + k;
            accv = fmaf(sT[v*TP + u], sM[v*SP + u], accv);
        }
        sPart[tid] = accv;
    }
    __syncthreads();
    if (tid < 128) {
        float s = 0.f;
#pragma unroll
        for (int k = 0; k < 8; k++) s += sPart[tid + 128*k];
        sV[1][tid] = tanhf(5.f * s);
    }
    __syncthreads();

    // ---- phase 7: blend + store (coalesced over u)
    {
        float* ob = out + (t_side ? (long)SZ : 0L) + b*CHW + h*Ww;
        const float* bb = (t_side ? xr : xl) + b*CHW + h*Ww;
        float Vv = sV[t_side][t_u];
        float om = 1.f - Vv;
#pragma unroll
        for (int j = 0; j < 8; j++) {
            float t0, t1;
            upk2(tacc[j], t0, t1);
            int c = t_c0 + 2*j;
            ob[c*HW + t_u]     = fmaf(bb[c*HW + t_u],     om, t0*Vv);
            ob[(c+1)*HW + t_u] = fmaf(bb[(c+1)*HW + t_u], om, t1*Vv);
        }
    }
}

// ---------------- launcher ----------------
extern "C" void kernel_launch(void* const* d_in, const int* in_sizes, int n_in,
                              void* d_out, int out_size) {
    const float* xl    = (const float*)d_in[0];
    const float* xr    = (const float*)d_in[1];
    const float* gamma = (const float*)d_in[2];
    const float* beta  = (const float*)d_in[3];
    const float* rw1   = (const float*)d_in[4];
    const float* rb1   = (const float*)d_in[5];
    const float* rw2   = (const float*)d_in[6];
    const float* rb2   = (const float*)d_in[7];
    const float* qw    = (const float*)d_in[8];
    const float* qb    = (const float*)d_in[9];
    const float* kw    = (const float*)d_in[10];
    const float* kb    = (const float*)d_in[11];
    float* out = (float*)d_out;

    const int CONV_SMEM = (16*CICSZ + 2304) * 4;

    cudaFuncSetAttribute(k_conv3<true>,  cudaFuncAttributeMaxDynamicSharedMemorySize, CONV_SMEM);
    cudaFuncSetAttribute(k_conv3<false>, cudaFuncAttributeMaxDynamicSharedMemorySize, CONV_SMEM);
    cudaFuncSetAttribute(k_attn,         cudaFuncAttributeMaxDynamicSharedMemorySize, ATT_SMEM);

    k_bnstats<<<dim3(Cc, 2), 256>>>(xl, xr, gamma, beta);
    k_conv3<true ><<<dim3(Hh/TH, Gg, 2*Bn), 256, CONV_SMEM>>>(xl, xr, rw1, rb1);
    k_conv3<false><<<dim3(Hh/TH, Gg, 2*Bn), 256, CONV_SMEM>>>(xl, xr, rw2, rb2);
    k_attn<<<NR, NT, ATT_SMEM>>>(xl, xr, qw, qb, kw, kb, out);
}

// round 12
// speedup vs baseline: 1.0664x; 1.0664x over previous
#include <cuda_runtime.h>
#include <math.h>

#define Bn 8
#define Cc 64
#define Hh 128
#define Ww 128
#define Gg 4
#define CG 16
#define HW (Hh*Ww)          // 16384
#define CHW (Cc*HW)         // 1048576
#define SZ (Bn*CHW)         // 8388608
#define NR (Bn*Hh)          // 1024
#define TH 8                // rows per CTA (512 threads, 2 row-quads)
#define CROWS (TH+2)        // 10 staged rows
#define SP 129              // sS/sM pitch (odd -> conflict-free column walks)
#define AP 66               // sA pitch (even -> STS.64 output stores)
#define CP 136              // conv sIn pitch
#define CICSZ (CROWS*CP)    // 1360 floats per input channel

typedef unsigned long long u64;

__device__ __forceinline__ u64 pk2(float lo, float hi) {
    u64 r;
    asm("mov.b64 %0, {%1, %2};" : "=l"(r)
        : "r"(__float_as_uint(lo)), "r"(__float_as_uint(hi)));
    return r;
}
__device__ __forceinline__ void upk2(u64 p, float& lo, float& hi) {
    unsigned a, bq;
    asm("mov.b64 {%0, %1}, %2;" : "=r"(a), "=r"(bq) : "l"(p));
    lo = __uint_as_float(a); hi = __uint_as_float(bq);
}
#define FMA2(d, a, b) asm("fma.rn.f32x2 %0, %1, %2, %3;" : "=l"(d) : "l"(a), "l"(b), "l"(d))

// scratch (device globals; no allocation allowed)
__device__ float g_t[2*SZ];
__device__ float g_r[2*SZ];
__device__ float g_stats[2][2][Cc];

// ---------------- BN batch statistics ----------------
__global__ void __launch_bounds__(256) k_bnstats(const float* __restrict__ xl,
                                                 const float* __restrict__ xr,
                                                 const float* __restrict__ gamma,
                                                 const float* __restrict__ beta) {
    int c = blockIdx.x, side = blockIdx.y;
    const float* x = side ? xr : xl;
    int tid = threadIdx.x;
    float s = 0.f, s2 = 0.f;
    for (int b = 0; b < Bn; b++) {
        const float* p = x + b*CHW + c*HW;
        for (int i = tid; i < HW; i += 256) {
            float v = p[i];
            s += v; s2 = fmaf(v, v, s2);
        }
    }
    __shared__ float sh[256], sh2[256];
    sh[tid] = s; sh2[tid] = s2;
    __syncthreads();
    for (int off = 128; off; off >>= 1) {
        if (tid < off) { sh[tid] += sh[tid+off]; sh2[tid] += sh2[tid+off]; }
        __syncthreads();
    }
    if (tid == 0) {
        double N = (double)(Bn*HW);
        double m = (double)sh[0] / N;
        double var = (double)sh2[0] / N - m*m;
        double rstd = 1.0 / sqrt(var + 1e-5);
        float a = gamma[c] * (float)rstd;
        float d = beta[c] - a * (float)m;
        g_stats[side][0][c] = a;
        g_stats[side][1][c] = d;
    }
}

// ---------------- grouped 3x3 conv (FFMA2, 512 threads, TH=8) ----------------
template<bool FIRST>
__global__ void __launch_bounds__(512) k_conv3(const float* __restrict__ xl,
                                               const float* __restrict__ xr,
                                               const float* __restrict__ wgt,
                                               const float* __restrict__ bias) {
    int ty = blockIdx.x, g = blockIdx.y;
    int side = blockIdx.z >> 3, b = blockIdx.z & 7;
    const float* xraw = side ? xr : xl;
    const float* in   = FIRST ? xraw : (g_t + side*SZ);
    float* out        = FIRST ? (g_t + side*SZ) : (g_r + side*SZ);

    extern __shared__ float sm[];
    float* sIn = sm;                 // [16][10][136] = 21760
    float* sW2 = sm + 16*CICSZ;      // [ic][k][o] = 2304
    __shared__ float sa[CG], sd[CG];
    int tid = threadIdx.x;

    if (tid < CG) {
        sa[tid] = g_stats[side][0][g*CG + tid];
        sd[tid] = g_stats[side][1][g*CG + tid];
    }
    __syncthreads();

    // transposed weight load: sW2[(ic*9+k)*16 + o] = wgt[g][o][ic][k]
    for (int i = tid; i < 2304; i += 512) {
        int o = i & 15, rem = i >> 4;
        int k = rem % 9, ic = rem / 9;
        sW2[i] = wgt[g*2304 + (o*16 + ic)*9 + k];
    }

    // halo columns always zero
    for (int i = tid; i < 16*CROWS; i += 512) {
        int ic = i / CROWS, r = i - ic*CROWS;
        sIn[ic*CICSZ + r*CP + 3]   = 0.f;
        sIn[ic*CICSZ + r*CP + 132] = 0.f;
    }

    // vector staging: 160 row-slots / 16 row-threads
    {
        int x4 = tid & 31, rowid = tid >> 5;
        int y0 = ty*TH - 1;
        const float* inb = in + b*CHW + g*CG*HW;
#pragma unroll
        for (int s = rowid; s < 16*CROWS; s += 16) {
            int ic = s / CROWS, r = s - ic*CROWS;
            int y = y0 + r;
            float4 v4 = make_float4(0.f, 0.f, 0.f, 0.f);
            if ((unsigned)y < (unsigned)Hh) {
                v4 = *(const float4*)(inb + ic*HW + y*Ww + x4*4);
                if (FIRST) {
                    float a = sa[ic], d = sd[ic];
                    v4.x = fmaf(a, v4.x, d);
                    v4.y = fmaf(a, v4.y, d);
                    v4.z = fmaf(a, v4.z, d);
                    v4.w = fmaf(a, v4.w, d);
                }
            }
            *(float4*)(sIn + ic*CICSZ + r*CP + 4 + x4*4) = v4;
        }
    }
    __syncthreads();

    int xcol = tid & 127, half = (tid >> 7) & 1, rq = tid >> 8;   // rq: row quad 0/1
    int rbase = rq*4;
    u64 acc2[4][4];
#pragma unroll
    for (int o2 = 0; o2 < 4; o2++) {
        u64 bp = pk2(bias[g*CG + half*8 + 2*o2], bias[g*CG + half*8 + 2*o2 + 1]);
#pragma unroll
        for (int r = 0; r < 4; r++) acc2[o2][r] = bp;
    }

    for (int ic = 0; ic < CG; ic++) {
        const float* ip = sIn + ic*CICSZ + rbase*CP;
#pragma unroll
        for (int k = 0; k < 9; k++) {
            int dy = k / 3, dx = k - dy*3;
            const ulonglong2* wq = (const ulonglong2*)(sW2 + (ic*9 + k)*16 + half*8);
            ulonglong2 wA = wq[0], wB = wq[1];
#pragma unroll
            for (int r = 0; r < 4; r++) {
                float iv = ip[(r+dy)*CP + xcol + 3 + dx];
                u64 piv = pk2(iv, iv);
                FMA2(acc2[0][r], wA.x, piv);
                FMA2(acc2[1][r], wA.y, piv);
                FMA2(acc2[2][r], wB.x, piv);
                FMA2(acc2[3][r], wB.y, piv);
            }
        }
    }

    int ybase = ty*TH + rbase;
#pragma unroll
    for (int o2 = 0; o2 < 4; o2++) {
        int ocl0 = half*8 + 2*o2;
        int gbase = b*CHW + (g*CG + ocl0)*HW + ybase*Ww + xcol;
#pragma unroll
        for (int r = 0; r < 4; r++) {
            float v0, v1;
            upk2(acc2[o2][r], v0, v1);
            if (FIRST) {
                v0 = v0 > 0.f ? v0 : 0.1f*v0;
                v1 = v1 > 0.f ? v1 : 0.1f*v1;
            } else {
                v0 += fmaf(sa[ocl0],   xraw[gbase + r*Ww],      sd[ocl0]);
                v1 += fmaf(sa[ocl0+1], xraw[gbase + HW + r*Ww], sd[ocl0+1]);
            }
            out[gbase + r*Ww]      = v0;
            out[gbase + HW + r*Ww] = v1;
        }
    }
}

// ---------------- fused attention (exact R9 structure: best measured 296us) ----------------
// smem (floats): sA[128][66]=8448 @0 | sB[64][132]=8448 @8448 | sS[128][129] @16896
//                sXl @33408 | sXr @42112 ; sM[128][129] overlays @0
#define ATT_SMEM (50816*4)
#define NT 1024
__global__ void __launch_bounds__(NT) k_attn(const float* __restrict__ xl,
                                             const float* __restrict__ xr,
                                             const float* __restrict__ qw, const float* __restrict__ qb,
                                             const float* __restrict__ kw, const float* __restrict__ kb,
                                             float* __restrict__ out) {
    int n = blockIdx.x, b = n >> 7, h = n & 127;
    extern __shared__ float sm[];
    float* sA  = sm;
    float* sB  = sm + 8448;
    float* sS  = sm + 16896;
    float* sXl = sm + 33408;
    float* sXr = sm + 42112;
    float* sM  = sm;                 // overlay
    __shared__ float sWq[2048];      // [side][i][o]
    __shared__ float sBias[128];
    __shared__ float sMean[128];
    __shared__ float sV[2][128];
    __shared__ float sPart[NT];
    int tid = threadIdx.x, lane = tid & 31, w = tid >> 5;

    // ---- phase 0: weights/bias (sync), then X staging + QK conv with direct LDG
    for (int idx = tid; idx < 2048; idx += NT) {
        int side = idx >> 10, rem = idx & 1023, i = rem >> 6, o = rem & 63;
        sWq[idx] = (side ? kw : qw)[o*16 + i];
    }
    if (tid < 64) { sBias[tid] = qb[tid]; sBias[64 + tid] = kb[tid]; }
    __syncthreads();

    // X staging
    for (int idx = tid; idx < 8192; idx += NT) {
        int c = idx >> 7, x = idx & 127;
        sXl[x*68 + c] = xl[b*CHW + c*HW + h*Ww + x];
        sXr[x*68 + c] = xr[b*CHW + c*HW + h*Ww + x];
    }

    // ---- phase 1: grouped 1x1 Q/K conv, one thread per (side,g,x), R from global
    {
        int side = tid >> 9, rem = tid & 511;
        int g = rem >> 7, x = rem & 127;
        const float* Rg = (side ? g_r + SZ : g_r) + b*CHW + h*Ww + g*16*HW + x;
        const u64* bp = (const u64*)(sBias + side*64 + g*16);
        u64 acc[8];
#pragma unroll
        for (int j = 0; j < 8; j++) acc[j] = bp[j];
#pragma unroll
        for (int i = 0; i < 16; i++) {
            float rv = Rg[(unsigned)(i*HW)];
            u64 prv = pk2(rv, rv);
            const u64* wp = (const u64*)(sWq + side*1024 + i*64 + g*16);
#pragma unroll
            for (int j = 0; j < 8; j++) FMA2(acc[j], wp[j], prv);
        }
        if (side == 0) {
            u64* dst = (u64*)(sA + x*AP + g*16);
#pragma unroll
            for (int j = 0; j < 8; j++) dst[j] = acc[j];
        } else {
            float* dst = sB + (g*16)*132 + x;
#pragma unroll
            for (int j = 0; j < 8; j++) {
                float a0, a1; upk2(acc[j], a0, a1);
                dst[(2*j)*132]   = a0;
                dst[(2*j+1)*132] = a1;
            }
        }
    }
    __syncthreads();

    // ---- phase 2: per-channel row means, subtract
    for (int task = w; task < 128; task += 32) {
        float s = 0.f;
        if (task < 64) {
#pragma unroll
            for (int k = 0; k < 4; k++) s += sA[(lane + 32*k)*AP + task];
        } else {
#pragma unroll
            for (int k = 0; k < 4; k++) s += sB[(task - 64)*132 + lane + 32*k];
        }
#pragma unroll
        for (int off = 16; off; off >>= 1) s += __shfl_xor_sync(0xffffffffu, s, off);
        if (lane == 0) sMean[task] = s * (1.f/128.f);
    }
    __syncthreads();
    for (int idx = tid; idx < 8192; idx += NT) {
        int c = idx >> 7, u = idx & 127;
        sA[u*AP + c]  -= sMean[c];
        sB[c*132 + u] -= sMean[64 + c];
    }
    __syncthreads();

    // ---- phase 3: score GEMM, warp owns 4 rows; row softmax from regs
    float mrow[4][4];
    {
        int u0 = w*4;
        int v0 = lane*4;
        u64 acc2[4][2];
#pragma unroll
        for (int r = 0; r < 4; r++) { acc2[r][0] = 0ull; acc2[r][1] = 0ull; }
        for (int c = 0; c < 64; c++) {
            const ulonglong2* kp = (const ulonglong2*)(sB + c*132 + v0);
            ulonglong2 bv = kp[0];
#pragma unroll
            for (int r = 0; r < 4; r++) {
                float a = sA[(u0 + r)*AP + c];
                u64 pa = pk2(a, a);
                FMA2(acc2[r][0], pa, bv.x);
                FMA2(acc2[r][1], pa, bv.y);
            }
        }
#pragma unroll
        for (int r = 0; r < 4; r++) {
            float x4[4];
            upk2(acc2[r][0], x4[0], x4[1]);
            upk2(acc2[r][1], x4[2], x4[3]);
            float* sp = sS + (u0 + r)*SP + v0;
            sp[0] = x4[0]; sp[1] = x4[1]; sp[2] = x4[2]; sp[3] = x4[3];
            float m = fmaxf(fmaxf(x4[0], x4[1]), fmaxf(x4[2], x4[3]));
#pragma unroll
            for (int off = 16; off; off >>= 1) m = fmaxf(m, __shfl_xor_sync(0xffffffffu, m, off));
            float e0 = __expf(x4[0]-m), e1 = __expf(x4[1]-m), e2 = __expf(x4[2]-m), e3 = __expf(x4[3]-m);
            float s = e0 + e1 + e2 + e3;
#pragma unroll
            for (int off = 16; off; off >>= 1) s += __shfl_xor_sync(0xffffffffu, s, off);
            float inv = 1.f / s;
            mrow[r][0] = e0*inv; mrow[r][1] = e1*inv; mrow[r][2] = e2*inv; mrow[r][3] = e3*inv;
        }
    }
    __syncthreads();

    // ---- phase 4: store M_rl rows from regs + column softmax
    {
        int u0 = w*4, v0 = lane*4;
#pragma unroll
        for (int r = 0; r < 4; r++) {
            float* mp = sM + (u0 + r)*SP + v0;
            mp[0] = mrow[r][0]; mp[1] = mrow[r][1]; mp[2] = mrow[r][2]; mp[3] = mrow[r][3];
        }
    }
    for (int c = w; c < 128; c += 32) {
        float x4[4]; float m = -1e30f;
#pragma unroll
        for (int k = 0; k < 4; k++) { x4[k] = sS[(lane + 32*k)*SP + c]; m = fmaxf(m, x4[k]); }
#pragma unroll
        for (int off = 16; off; off >>= 1) m = fmaxf(m, __shfl_xor_sync(0xffffffffu, m, off));
        float e4[4]; float s = 0.f;
#pragma unroll
        for (int k = 0; k < 4; k++) { e4[k] = __expf(x4[k] - m); s += e4[k]; }
#pragma unroll
        for (int off = 16; off; off >>= 1) s += __shfl_xor_sync(0xffffffffu, s, off);
        float inv = 1.f / s;
#pragma unroll
        for (int k = 0; k < 4; k++) sS[(lane + 32*k)*SP + c] = e4[k] * inv;
    }
    __syncthreads();

    // ---- phase 5: validity maps
    {
        int task = tid & 255, vq = tid >> 8;
        int side = task >> 7, u = task & 127;
        int vA = vq*32, vB = vA + 32;
        float accv = 0.f;
        if (side == 0) {
            for (int v = vA; v < vB; v++) {
                float A = 0.f;
#pragma unroll
                for (int d = -2; d <= 2; d++) {
                    int uu = u + d;
                    if ((unsigned)uu < 128u) A += sM[uu*SP + v];
                }
                accv += A * sS[u*SP + v];
            }
        } else {
            for (int v = vA; v < vB; v++) {
                float A = 0.f;
#pragma unroll
                for (int d = -2; d <= 2; d++) {
                    int uu = u + d;
                    if ((unsigned)uu < 128u) A += sS[v*SP + uu];
                }
                accv += A * sM[v*SP + u];
            }
        }
        sPart[tid] = accv;
    }
    __syncthreads();
    if (tid < 256) {
        int side = tid >> 7, u = tid & 127;
        sV[side][u] = tanhf(5.f * (sPart[tid] + sPart[tid + 256] + sPart[tid + 512] + sPart[tid + 768]));
    }
    __syncthreads();

    // ---- phase 6: transport GEMMs + blend (2u x 8c, X broadcast)
    {
        int side = w >> 4, wl = w & 15;
        int c0 = (wl & 7)*8, uh = wl >> 3;
        const float* X = side ? sXl : sXr;
        u64 acc2[2][4];
#pragma unroll
        for (int i = 0; i < 2; i++)
#pragma unroll
            for (int j = 0; j < 4; j++) acc2[i][j] = 0ull;

        int u0 = lane + 32*uh;
        for (int v = 0; v < 128; v++) {
            u64 pa[2];
            if (side == 0) {
#pragma unroll
                for (int i = 0; i < 2; i++) {
                    float a = sM[(u0 + 64*i)*SP + v];
                    pa[i] = pk2(a, a);
                }
            } else {
#pragma unroll
                for (int i = 0; i < 2; i++) {
                    float a = sS[v*SP + u0 + 64*i];
                    pa[i] = pk2(a, a);
                }
            }
            const ulonglong2* xp = (const ulonglong2*)(X + v*68 + c0);
            ulonglong2 xA = xp[0], xB = xp[1];
#pragma unroll
            for (int i = 0; i < 2; i++) {
                FMA2(acc2[i][0], pa[i], xA.x);
                FMA2(acc2[i][1], pa[i], xA.y);
                FMA2(acc2[i][2], pa[i], xB.x);
                FMA2(acc2[i][3], pa[i], xB.y);
            }
        }

        float* ob = out + (side ? (long)SZ : 0L) + b*CHW + h*Ww;
        const float* bb = (side ? xr : xl) + b*CHW + h*Ww;
#pragma unroll
        for (int i = 0; i < 2; i++) {
            int u = u0 + 64*i;
            float Vv = sV[side][u];
#pragma unroll
            for (int j = 0; j < 4; j++) {
                float t0, t1;
                upk2(acc2[i][j], t0, t1);
                int c = c0 + 2*j;
                ob[c*HW + u]      = fmaf(bb[c*HW + u],      1.f - Vv, t0*Vv);
                ob[(c+1)*HW + u]  = fmaf(bb[(c+1)*HW + u],  1.f - Vv, t1*Vv);
            }
        }
    }
}

// ---------------- launcher ----------------
extern "C" void kernel_launch(void* const* d_in, const int* in_sizes, int n_in,
                              void* d_out, int out_size) {
    const float* xl    = (const float*)d_in[0];
    const float* xr    = (const float*)d_in[1];
    const float* gamma = (const float*)d_in[2];
    const float* beta  = (const float*)d_in[3];
    const float* rw1   = (const float*)d_in[4];
    const float* rb1   = (const float*)d_in[5];
    const float* rw2   = (const float*)d_in[6];
    const float* rb2   = (const float*)d_in[7];
    const float* qw    = (const float*)d_in[8];
    const float* qb    = (const float*)d_in[9];
    const float* kw    = (const float*)d_in[10];
    const float* kb    = (const float*)d_in[11];
    float* out = (float*)d_out;

    const int CONV_SMEM = (16*CICSZ + 2304) * 4;   // 96256

    cudaFuncSetAttribute(k_conv3<true>,  cudaFuncAttributeMaxDynamicSharedMemorySize, CONV_SMEM);
    cudaFuncSetAttribute(k_conv3<false>, cudaFuncAttributeMaxDynamicSharedMemorySize, CONV_SMEM);
    cudaFuncSetAttribute(k_attn,         cudaFuncAttributeMaxDynamicSharedMemorySize, ATT_SMEM);

    k_bnstats<<<dim3(Cc, 2), 256>>>(xl, xr, gamma, beta);
    k_conv3<true ><<<dim3(Hh/TH, Gg, 2*Bn), 512, CONV_SMEM>>>(xl, xr, rw1, rb1);
    k_conv3<false><<<dim3(Hh/TH, Gg, 2*Bn), 512, CONV_SMEM>>>(xl, xr, rw2, rb2);
    k_attn<<<NR, NT, ATT_SMEM>>>(xl, xr, qw, qb, kw, kb, out);
}

// round 15
// speedup vs baseline: 1.1019x; 1.0333x over previous
#include <cuda_runtime.h>
#include <math.h>

#define Bn 8
#define Cc 64
#define Hh 128
#define Ww 128
#define Gg 4
#define CG 16
#define HW (Hh*Ww)          // 16384
#define CHW (Cc*HW)         // 1048576
#define SZ (Bn*CHW)         // 8388608
#define NR (Bn*Hh)          // 1024
#define TH 8                // conv rows per CTA (512 threads)
#define CROWS (TH+2)
#define SP 129              // sS/sM pitch (odd -> conflict-free column walks)
#define AP 68               // sA pitch (16B-aligned rows for LDS.128 a-loads)
#define CP 136
#define CICSZ (CROWS*CP)

typedef unsigned long long u64;

__device__ __forceinline__ u64 pk2(float lo, float hi) {
    u64 r;
    asm("mov.b64 %0, {%1, %2};" : "=l"(r)
        : "r"(__float_as_uint(lo)), "r"(__float_as_uint(hi)));
    return r;
}
__device__ __forceinline__ void upk2(u64 p, float& lo, float& hi) {
    unsigned a, bq;
    asm("mov.b64 {%0, %1}, %2;" : "=r"(a), "=r"(bq) : "l"(p));
    lo = __uint_as_float(a); hi = __uint_as_float(bq);
}
#define FMA2(d, a, b) asm("fma.rn.f32x2 %0, %1, %2, %3;" : "=l"(d) : "l"(a), "l"(b), "l"(d))

__device__ float g_t[2*SZ];
__device__ float g_r[2*SZ];
__device__ float g_stats[2][2][Cc];

// ---------------- BN batch statistics (float4 loads) ----------------
__global__ void __launch_bounds__(256) k_bnstats(const float* __restrict__ xl,
                                                 const float* __restrict__ xr,
                                                 const float* __restrict__ gamma,
                                                 const float* __restrict__ beta) {
    int c = blockIdx.x, side = blockIdx.y;
    const float* x = side ? xr : xl;
    int tid = threadIdx.x;
    float s = 0.f, s2 = 0.f;
    for (int b = 0; b < Bn; b++) {
        const float4* p = (const float4*)(x + b*CHW + c*HW);
        for (int i = tid; i < HW/4; i += 256) {
            float4 v = p[i];
            s += v.x + v.y + v.z + v.w;
            s2 = fmaf(v.x, v.x, s2);
            s2 = fmaf(v.y, v.y, s2);
            s2 = fmaf(v.z, v.z, s2);
            s2 = fmaf(v.w, v.w, s2);
        }
    }
    __shared__ float sh[256], sh2[256];
    sh[tid] = s; sh2[tid] = s2;
    __syncthreads();
    for (int off = 128; off; off >>= 1) {
        if (tid < off) { sh[tid] += sh[tid+off]; sh2[tid] += sh2[tid+off]; }
        __syncthreads();
    }
    if (tid == 0) {
        double N = (double)(Bn*HW);
        double m = (double)sh[0] / N;
        double var = (double)sh2[0] / N - m*m;
        double rstd = 1.0 / sqrt(var + 1e-5);
        float a = gamma[c] * (float)rstd;
        float d = beta[c] - a * (float)m;
        g_stats[side][0][c] = a;
        g_stats[side][1][c] = d;
    }
}

// ---------------- grouped 3x3 conv (R12, unchanged) ----------------
template<bool FIRST>
__global__ void __launch_bounds__(512) k_conv3(const float* __restrict__ xl,
                                               const float* __restrict__ xr,
                                               const float* __restrict__ wgt,
                                               const float* __restrict__ bias) {
    int ty = blockIdx.x, g = blockIdx.y;
    int side = blockIdx.z >> 3, b = blockIdx.z & 7;
    const float* xraw = side ? xr : xl;
    const float* in   = FIRST ? xraw : (g_t + side*SZ);
    float* out        = FIRST ? (g_t + side*SZ) : (g_r + side*SZ);

    extern __shared__ float sm[];
    float* sIn = sm;
    float* sW2 = sm + 16*CICSZ;
    __shared__ float sa[CG], sd[CG];
    int tid = threadIdx.x;

    if (tid < CG) {
        sa[tid] = g_stats[side][0][g*CG + tid];
        sd[tid] = g_stats[side][1][g*CG + tid];
    }
    __syncthreads();

    for (int i = tid; i < 2304; i += 512) {
        int o = i & 15, rem = i >> 4;
        int k = rem % 9, ic = rem / 9;
        sW2[i] = wgt[g*2304 + (o*16 + ic)*9 + k];
    }

    for (int i = tid; i < 16*CROWS; i += 512) {
        int ic = i / CROWS, r = i - ic*CROWS;
        sIn[ic*CICSZ + r*CP + 3]   = 0.f;
        sIn[ic*CICSZ + r*CP + 132] = 0.f;
    }

    {
        int x4 = tid & 31, rowid = tid >> 5;
        int y0 = ty*TH - 1;
        const float* inb = in + b*CHW + g*CG*HW;
#pragma unroll
        for (int s = rowid; s < 16*CROWS; s += 16) {
            int ic = s / CROWS, r = s - ic*CROWS;
            int y = y0 + r;
            float4 v4 = make_float4(0.f, 0.f, 0.f, 0.f);
            if ((unsigned)y < (unsigned)Hh) {
                v4 = *(const float4*)(inb + ic*HW + y*Ww + x4*4);
                if (FIRST) {
                    float a = sa[ic], d = sd[ic];
                    v4.x = fmaf(a, v4.x, d);
                    v4.y = fmaf(a, v4.y, d);
                    v4.z = fmaf(a, v4.z, d);
                    v4.w = fmaf(a, v4.w, d);
                }
            }
            *(float4*)(sIn + ic*CICSZ + r*CP + 4 + x4*4) = v4;
        }
    }
    __syncthreads();

    int xcol = tid & 127, half = (tid >> 7) & 1, rq = tid >> 8;
    int rbase = rq*4;
    u64 acc2[4][4];
#pragma unroll
    for (int o2 = 0; o2 < 4; o2++) {
        u64 bp = pk2(bias[g*CG + half*8 + 2*o2], bias[g*CG + half*8 + 2*o2 + 1]);
#pragma unroll
        for (int r = 0; r < 4; r++) acc2[o2][r] = bp;
    }

    for (int ic = 0; ic < CG; ic++) {
        const float* ip = sIn + ic*CICSZ + rbase*CP;
#pragma unroll
        for (int k = 0; k < 9; k++) {
            int dy = k / 3, dx = k - dy*3;
            const ulonglong2* wq = (const ulonglong2*)(sW2 + (ic*9 + k)*16 + half*8);
            ulonglong2 wA = wq[0], wB = wq[1];
#pragma unroll
            for (int r = 0; r < 4; r++) {
                float iv = ip[(r+dy)*CP + xcol + 3 + dx];
                u64 piv = pk2(iv, iv);
                FMA2(acc2[0][r], wA.x, piv);
                FMA2(acc2[1][r], wA.y, piv);
                FMA2(acc2[2][r], wB.x, piv);
                FMA2(acc2[3][r], wB.y, piv);
            }
        }
    }

    int ybase = ty*TH + rbase;
#pragma unroll
    for (int o2 = 0; o2 < 4; o2++) {
        int ocl0 = half*8 + 2*o2;
        int gbase = b*CHW + (g*CG + ocl0)*HW + ybase*Ww + xcol;
#pragma unroll
        for (int r = 0; r < 4; r++) {
            float v0, v1;
            upk2(acc2[o2][r], v0, v1);
            if (FIRST) {
                v0 = v0 > 0.f ? v0 : 0.1f*v0;
                v1 = v1 > 0.f ? v1 : 0.1f*v1;
            } else {
                v0 += fmaf(sa[ocl0],   xraw[gbase + r*Ww],      sd[ocl0]);
                v1 += fmaf(sa[ocl0+1], xraw[gbase + HW + r*Ww], sd[ocl0+1]);
            }
            out[gbase + r*Ww]      = v0;
            out[gbase + HW + r*Ww] = v1;
        }
    }
}

// ---------------- fused attention ----------------
// smem (floats): sA[128][68]=8704 @0 | sB[64][132]=8448 @8704 | sS[128][129]=16512 @17152
//                sXl @33664 | sXr @42368 ; end 51072 ; sM[128][129] overlays @0
#define ATT_SMEM (51072*4)
#define NT 1024
__global__ void __launch_bounds__(NT) k_attn(const float* __restrict__ xl,
                                             const float* __restrict__ xr,
                                             const float* __restrict__ qw, const float* __restrict__ qb,
                                             const float* __restrict__ kw, const float* __restrict__ kb,
                                             float* __restrict__ out) {
    int n = blockIdx.x, b = n >> 7, h = n & 127;
    extern __shared__ float sm[];
    float* sA  = sm;
    float* sB  = sm + 8704;
    float* sS  = sm + 17152;
    float* sXl = sm + 33664;
    float* sXr = sm + 42368;
    float* sM  = sm;                 // overlay
    __shared__ float sWq[2048];      // [side][i][o]
    __shared__ float sBias[128];
    __shared__ float sMean[128];
    __shared__ float sV[2][128];
    __shared__ float sPart[NT];
    int tid = threadIdx.x, lane = tid & 31, w = tid >> 5;

    // ---- phase 0: weights/bias
    for (int idx = tid; idx < 2048; idx += NT) {
        int side = idx >> 10, rem = idx & 1023, i = rem >> 6, o = rem & 63;
        sWq[idx] = (side ? kw : qw)[o*16 + i];
    }
    if (tid < 64) { sBias[tid] = qb[tid]; sBias[64 + tid] = kb[tid]; }
    __syncthreads();

    // X staging
    for (int idx = tid; idx < 8192; idx += NT) {
        int c = idx >> 7, x = idx & 127;
        sXl[x*68 + c] = xl[b*CHW + c*HW + h*Ww + x];
        sXr[x*68 + c] = xr[b*CHW + c*HW + h*Ww + x];
    }

    // ---- phase 1: grouped 1x1 Q/K conv, R from global, LDS.128 weight broadcasts
    {
        int side = tid >> 9, rem = tid & 511;
        int g = rem >> 7, x = rem & 127;
        const float* Rg = (side ? g_r + SZ : g_r) + b*CHW + h*Ww + g*16*HW + x;
        const u64* bp = (const u64*)(sBias + side*64 + g*16);
        u64 acc[8];
#pragma unroll
        for (int j = 0; j < 8; j++) acc[j] = bp[j];
#pragma unroll
        for (int i = 0; i < 16; i++) {
            float rv = Rg[(unsigned)(i*HW)];
            u64 prv = pk2(rv, rv);
            const ulonglong2* wp2 = (const ulonglong2*)(sWq + side*1024 + i*64 + g*16);
            ulonglong2 wA = wp2[0], wB = wp2[1], wC = wp2[2], wD = wp2[3];
            FMA2(acc[0], wA.x, prv);
            FMA2(acc[1], wA.y, prv);
            FMA2(acc[2], wB.x, prv);
            FMA2(acc[3], wB.y, prv);
            FMA2(acc[4], wC.x, prv);
            FMA2(acc[5], wC.y, prv);
            FMA2(acc[6], wD.x, prv);
            FMA2(acc[7], wD.y, prv);
        }
        if (side == 0) {
            u64* dst = (u64*)(sA + x*AP + g*16);
#pragma unroll
            for (int j = 0; j < 8; j++) dst[j] = acc[j];
        } else {
            float* dst = sB + (g*16)*132 + x;
#pragma unroll
            for (int j = 0; j < 8; j++) {
                float a0, a1; upk2(acc[j], a0, a1);
                dst[(2*j)*132]   = a0;
                dst[(2*j+1)*132] = a1;
            }
        }
    }
    __syncthreads();

    // ---- phase 2: per-channel row means (sA: lane=c coalesced; sB: original pattern)
    if (w < 2) {
        int c = w*32 + lane;
        float s = 0.f;
        for (int u = 0; u < 128; u++) s += sA[u*AP + c];
        sMean[c] = s * (1.f/128.f);
    } else {
        for (int c = w - 2; c < 64; c += 30) {
            float s = 0.f;
#pragma unroll
            for (int k = 0; k < 4; k++) s += sB[c*132 + lane + 32*k];
#pragma unroll
            for (int off = 16; off; off >>= 1) s += __shfl_xor_sync(0xffffffffu, s, off);
            if (lane == 0) sMean[64 + c] = s * (1.f/128.f);
        }
    }
    __syncthreads();
    // subtract (both coalesced)
    for (int idx = tid; idx < 8192; idx += NT) {
        int u = idx >> 6, c = idx & 63;
        sA[u*AP + c] -= sMean[c];
    }
    for (int idx = tid; idx < 8192; idx += NT) {
        int c = idx >> 7, u = idx & 127;
        sB[c*132 + u] -= sMean[64 + c];
    }
    __syncthreads();

    // ---- phase 3: score GEMM, warp owns 4 rows, c-quad vectorized a-loads; row softmax from regs
    float mrow[4][4];
    {
        int u0 = w*4;
        int v0 = lane*4;
        u64 acc2[4][2];
#pragma unroll
        for (int r = 0; r < 4; r++) { acc2[r][0] = 0ull; acc2[r][1] = 0ull; }
        for (int c0 = 0; c0 < 64; c0 += 4) {
            float4 a4[4];
#pragma unroll
            for (int r = 0; r < 4; r++)
                a4[r] = *(const float4*)(sA + (u0 + r)*AP + c0);
#pragma unroll
            for (int j = 0; j < 4; j++) {
                ulonglong2 bv = *(const ulonglong2*)(sB + (c0 + j)*132 + v0);
#pragma unroll
                for (int r = 0; r < 4; r++) {
                    float a = ((const float*)&a4[r])[j];
                    u64 pa = pk2(a, a);
                    FMA2(acc2[r][0], pa, bv.x);
                    FMA2(acc2[r][1], pa, bv.y);
                }
            }
        }
#pragma unroll
        for (int r = 0; r < 4; r++) {
            float x4[4];
            upk2(acc2[r][0], x4[0], x4[1]);
            upk2(acc2[r][1], x4[2], x4[3]);
            float* sp = sS + (u0 + r)*SP + v0;
            sp[0] = x4[0]; sp[1] = x4[1]; sp[2] = x4[2]; sp[3] = x4[3];
            float m = fmaxf(fmaxf(x4[0], x4[1]), fmaxf(x4[2], x4[3]));
#pragma unroll
            for (int off = 16; off; off >>= 1) m = fmaxf(m, __shfl_xor_sync(0xffffffffu, m, off));
            float e0 = __expf(x4[0]-m), e1 = __expf(x4[1]-m), e2 = __expf(x4[2]-m), e3 = __expf(x4[3]-m);
            float s = e0 + e1 + e2 + e3;
#pragma unroll
            for (int off = 16; off; off >>= 1) s += __shfl_xor_sync(0xffffffffu, s, off);
            float inv = 1.f / s;
            mrow[r][0] = e0*inv; mrow[r][1] = e1*inv; mrow[r][2] = e2*inv; mrow[r][3] = e3*inv;
        }
    }
    __syncthreads();

    // ---- phase 4: store M_rl from regs + column softmax
    {
        int u0 = w*4, v0 = lane*4;
#pragma unroll
        for (int r = 0; r < 4; r++) {
            float* mp = sM + (u0 + r)*SP + v0;
            mp[0] = mrow[r][0]; mp[1] = mrow[r][1]; mp[2] = mrow[r][2]; mp[3] = mrow[r][3];
        }
    }
    for (int c = w; c < 128; c += 32) {
        float x4[4]; float m = -1e30f;
#pragma unroll
        for (int k = 0; k < 4; k++) { x4[k] = sS[(lane + 32*k)*SP + c]; m = fmaxf(m, x4[k]); }
#pragma unroll
        for (int off = 16; off; off >>= 1) m = fmaxf(m, __shfl_xor_sync(0xffffffffu, m, off));
        float e4[4]; float s = 0.f;
#pragma unroll
        for (int k = 0; k < 4; k++) { e4[k] = __expf(x4[k] - m); s += e4[k]; }
#pragma unroll
        for (int off = 16; off; off >>= 1) s += __shfl_xor_sync(0xffffffffu, s, off);
        float inv = 1.f / s;
#pragma unroll
        for (int k = 0; k < 4; k++) sS[(lane + 32*k)*SP + c] = e4[k] * inv;
    }
    __syncthreads();

    // ---- phase 5: validity maps (R9)
    {
        int task = tid & 255, vq = tid >> 8;
        int side = task >> 7, u = task & 127;
        int vA = vq*32, vB = vA + 32;
        float accv = 0.f;
        if (side == 0) {
            for (int v = vA; v < vB; v++) {
                float A = 0.f;
#pragma unroll
                for (int d = -2; d <= 2; d++) {
                    int uu = u + d;
                    if ((unsigned)uu < 128u) A += sM[uu*SP + v];
                }
                accv += A * sS[u*SP + v];
            }
        } else {
            for (int v = vA; v < vB; v++) {
                float A = 0.f;
#pragma unroll
                for (int d = -2; d <= 2; d++) {
                    int uu = u + d;
                    if ((unsigned)uu < 128u) A += sS[v*SP + uu];
                }
                accv += A * sM[v*SP + u];
            }
        }
        sPart[tid] = accv;
    }
    __syncthreads();
    if (tid < 256) {
        int side = tid >> 7, u = tid & 127;
        sV[side][u] = tanhf(5.f * (sPart[tid] + sPart[tid + 256] + sPart[tid + 512] + sPart[tid + 768]));
    }
    __syncthreads();

    // ---- phase 6: transport GEMMs + blend (R9)
    {
        int side = w >> 4, wl = w & 15;
        int c0 = (wl & 7)*8, uh = wl >> 3;
        const float* X = side ? sXl : sXr;
        u64 acc2[2][4];
#pragma unroll
        for (int i = 0; i < 2; i++)
#pragma unroll
            for (int j = 0; j < 4; j++) acc2[i][j] = 0ull;

        int u0 = lane + 32*uh;
        for (int v = 0; v < 128; v++) {
            u64 pa[2];
            if (side == 0) {
#pragma unroll
                for (int i = 0; i < 2; i++) {
                    float a = sM[(u0 + 64*i)*SP + v];
                    pa[i] = pk2(a, a);
                }
            } else {
#pragma unroll
                for (int i = 0; i < 2; i++) {
                    float a = sS[v*SP + u0 + 64*i];
                    pa[i] = pk2(a, a);
                }
            }
            const ulonglong2* xp = (const ulonglong2*)(X + v*68 + c0);
            ulonglong2 xA = xp[0], xB = xp[1];
#pragma unroll
            for (int i = 0; i < 2; i++) {
                FMA2(acc2[i][0], pa[i], xA.x);
                FMA2(acc2[i][1], pa[i], xA.y);
                FMA2(acc2[i][2], pa[i], xB.x);
                FMA2(acc2[i][3], pa[i], xB.y);
            }
        }

        float* ob = out + (side ? (long)SZ : 0L) + b*CHW + h*Ww;
        const float* bb = (side ? xr : xl) + b*CHW + h*Ww;
#pragma unroll
        for (int i = 0; i < 2; i++) {
            int u = u0 + 64*i;
            float Vv = sV[side][u];
#pragma unroll
            for (int j = 0; j < 4; j++) {
                float t0, t1;
                upk2(acc2[i][j], t0, t1);
                int c = c0 + 2*j;
                ob[c*HW + u]      = fmaf(bb[c*HW + u],      1.f - Vv, t0*Vv);
                ob[(c+1)*HW + u]  = fmaf(bb[(c+1)*HW + u],  1.f - Vv, t1*Vv);
            }
        }
    }
}

// ---------------- launcher ----------------
extern "C" void kernel_launch(void* const* d_in, const int* in_sizes, int n_in,
                              void* d_out, int out_size) {
    const float* xl    = (const float*)d_in[0];
    const float* xr    = (const float*)d_in[1];
    const float* gamma = (const float*)d_in[2];
    const float* beta  = (const float*)d_in[3];
    const float* rw1   = (const float*)d_in[4];
    const float* rb1   = (const float*)d_in[5];
    const float* rw2   = (const float*)d_in[6];
    const float* rb2   = (const float*)d_in[7];
    const float* qw    = (const float*)d_in[8];
    const float* qb    = (const float*)d_in[9];
    const float* kw    = (const float*)d_in[10];
    const float* kb    = (const float*)d_in[11];
    float* out = (float*)d_out;

    const int CONV_SMEM = (16*CICSZ + 2304) * 4;   // 96256

    cudaFuncSetAttribute(k_conv3<true>,  cudaFuncAttributeMaxDynamicSharedMemorySize, CONV_SMEM);
    cudaFuncSetAttribute(k_conv3<false>, cudaFuncAttributeMaxDynamicSharedMemorySize, CONV_SMEM);
    cudaFuncSetAttribute(k_attn,         cudaFuncAttributeMaxDynamicSharedMemorySize, ATT_SMEM);

    k_bnstats<<<dim3(Cc, 2), 256>>>(xl, xr, gamma, beta);
    k_conv3<true ><<<dim3(Hh/TH, Gg, 2*Bn), 512, CONV_SMEM>>>(xl, xr, rw1, rb1);
    k_conv3<false><<<dim3(Hh/TH, Gg, 2*Bn), 512, CONV_SMEM>>>(xl, xr, rw2, rb2);
    k_attn<<<NR, NT, ATT_SMEM>>>(xl, xr, qw, qb, kw, kb, out);
}